// round 9
// baseline (speedup 1.0000x reference)
#include <cuda_runtime.h>
#include <cuda_fp16.h>
#include <cstdint>

// ---------------- static scratch ----------------
#define TBITS 21
#define TSIZE (1u << TBITS)
#define TMASK (TSIZE - 1u)
#define EMPTYK 0xFFFFFFFFu
#define MAXE 1050624
#define MAXN 40960
#define DUPCAP 65536

__device__ unsigned int  g_hkey[TSIZE];
__device__ unsigned char g_dupflag[TSIZE];
__device__ int           g_dupid[TSIZE];
__device__ int           g_soe[MAXE];   // pass1: slot of edge; pass2: rev-offset code
__device__ __align__(16) float g_agg[MAXN * 64];
__device__ __align__(16) float g_dupsum[(size_t)DUPCAP * 64];
__device__ int           g_ndup;

// ---------------- helpers ----------------
__device__ __forceinline__ unsigned int mixh(unsigned int x) {
    x ^= x >> 16; x *= 0x7feb352du;
    x ^= x >> 15; x *= 0x846ca68bu;
    x ^= x >> 16; return x;
}

__device__ __forceinline__ void red4(float* p, float4 v) {
    asm volatile("red.global.add.v4.f32 [%0], {%1,%2,%3,%4};"
                 :: "l"(p), "f"(v.x), "f"(v.y), "f"(v.z), "f"(v.w) : "memory");
}

// fp16 split: x -> hi(f16x2) + lo(f16x2 of residual); elem .x in low half
__device__ __forceinline__ void cvt_split(float2 x, uint32_t& hi, uint32_t& lo) {
    __half2 h = __float22half2_rn(x);
    float2 hb = __half22float2(h);
    __half2 l = __floats2half2_rn(x.x - hb.x, x.y - hb.y);
    hi = *(uint32_t*)&h;
    lo = *(uint32_t*)&l;
}

__device__ __forceinline__ void mma16816(float* c, const uint32_t* a,
                                         uint32_t b0, uint32_t b1) {
    asm("mma.sync.aligned.m16n8k16.row.col.f32.f16.f16.f32 "
        "{%0,%1,%2,%3}, {%4,%5,%6,%7}, {%8,%9}, {%0,%1,%2,%3};"
        : "+f"(c[0]), "+f"(c[1]), "+f"(c[2]), "+f"(c[3])
        : "r"(a[0]), "r"(a[1]), "r"(a[2]), "r"(a[3]), "r"(b0), "r"(b1));
}

// ---------------- kernel: hash insert (thread per edge) ----------------
__global__ __launch_bounds__(256) void k_hash(const int* __restrict__ esrc,
                                              const int* __restrict__ edst,
                                              int nn, int E) {
    int i = blockIdx.x * 256 + threadIdx.x;
    if (i >= E) return;
    int s = esrc[i], d = edst[i];
    unsigned int key = (unsigned int)s * (unsigned int)nn + (unsigned int)d;
    unsigned int h = mixh(key) & TMASK;
    for (;;) {
        unsigned int prev = atomicCAS(&g_hkey[h], EMPTYK, key);
        if (prev == EMPTYK) break;
        if (prev == key) { g_dupflag[h] = 1; break; }
        h = (h + 1u) & TMASK;
    }
    g_soe[i] = (int)h;
}

// ---------------- kernel: coalesced v4 aggregation + dup claim/acc + rev encode ------
// Warp-per-32-edges. Aggregation: 16 lanes x float4 cover one 256B row; one
// LDG.128 + red.v4 warp-instruction covers TWO rows.
__global__ __launch_bounds__(256) void k_aggdup(const float* __restrict__ ef,
                                                const int* __restrict__ edst,
                                                int E) {
    const int lane = threadIdx.x & 31;
    const int wid  = threadIdx.x >> 5;
    const int nw   = gridDim.x * 8;
    const int half = lane >> 4;          // 0: row j, 1: row j+1
    const int col  = (lane & 15) * 4;    // float index within row

    for (int base = (blockIdx.x * 8 + wid) * 32; base < E; base += nw * 32) {
        int e = base + lane;
        bool v = e < E;
        int dst = v ? __ldg(&edst[e]) : 0;

        // ---- dup handling (per-thread, scattered but rare) ----
        if (v) {
            int slot = g_soe[e];
            int enc = -1;
            if (g_dupflag[slot]) {
                int d = g_dupid[slot];
                if (d < 0) {
                    int my = atomicAdd(&g_ndup, 1);
                    int old = atomicCAS(&g_dupid[slot], -1, my);
                    d = (old == -1) ? my : old;
                }
                if (d < DUPCAP) {
                    enc = d * 256;
                    const float4* row = (const float4*)(ef + (size_t)e * 64);
                    float* p = g_dupsum + (size_t)d * 64;
#pragma unroll
                    for (int c = 0; c < 16; c++) red4(p + 4 * c, row[c]);
                }
            }
            g_soe[e] = enc;
        }

        // ---- coalesced aggregation: 2 rows per warp-instruction ----
        int nvalid = min(32, E - base);
#pragma unroll 4
        for (int j = 0; j < 32; j += 2) {
            if (j >= nvalid) break;
            int r = j + half;
            int dj = __shfl_sync(0xFFFFFFFFu, dst, r);
            if (r < nvalid) {
                float4 x = *(const float4*)(ef + (size_t)(base + r) * 64 + col);
                red4(g_agg + (size_t)dj * 64 + col, x);
            }
        }
    }
}

// ---------------- fused: mirror-paired direct-fragment HMMA ----------------
// Warp-tile M=32 = 16 first-half edges + their 16 mirrors, N=64, K=128.
// Rev of row j (non-dup) = xf[j^2] (partner's ef pairs, already in registers).
// 32-bit byte offsets only; 3-product fp16 split: xh*wh + xl*wh + xh*wl.
__global__ __launch_bounds__(256, 2) void k_fused_mma(const float* __restrict__ ef,
                                                      const int* __restrict__ esrc,
                                                      const float* __restrict__ W,
                                                      const float* __restrict__ bias,
                                                      float* __restrict__ out, int E) {
    __shared__ uint4 Bf[8][8][32];   // [kb][nb][lane] = (bh0,bh1,bl0,bl1)  32KB

    const int tid  = threadIdx.x;
    const int lane = tid & 31;
    const int wid  = tid >> 5;
    const int q    = lane & 3;
    const int g    = lane >> 2;

    // W fragments: standard m16n8k16 k-map, N-permuted for float4 stores.
    for (int idx = tid; idx < 2048; idx += 256) {
        int kb = idx >> 8, nb = (idx >> 5) & 7, L = idx & 31;
        int qq = L & 3, nB = L >> 2;
        int n = 16 * (nb >> 1) + ((nB >> 1) << 2) + ((nb & 1) << 1) + (nB & 1);
        int k0 = kb * 16 + 2 * qq;
        uint32_t h0, l0, h1, l1;
        cvt_split(make_float2(W[k0 * 64 + n], W[(k0 + 1) * 64 + n]), h0, l0);
        cvt_split(make_float2(W[(k0 + 8) * 64 + n], W[(k0 + 9) * 64 + n]), h1, l1);
        Bf[kb][nb][L] = make_uint4(h0, h1, l0, l1);
    }
    __syncthreads();

    const int E2 = E >> 1;
    const uint32_t E2b = (uint32_t)E2 * 256u;
    const int ntiles = (E2 + 15) >> 4;

    for (int t = blockIdx.x * 8 + wid; t < ntiles; t += gridDim.x * 8) {
        const int base = t * 16;
        int f0 = base + g, f1 = base + 8 + g;
        bool v0 = f0 < E2, v1 = f1 < E2;
        int e0 = v0 ? f0 : 0, e1 = v1 ? f1 : 0;

        uint32_t oef[4], oagg[4], orev[4];
        oef[0] = (uint32_t)e0 * 256u;
        oef[1] = (uint32_t)e1 * 256u;
        oef[2] = oef[0] + E2b;
        oef[3] = oef[1] + E2b;
        oagg[0] = (uint32_t)__ldg(&esrc[e0]) * 256u;
        oagg[1] = (uint32_t)__ldg(&esrc[e1]) * 256u;
        oagg[2] = (uint32_t)__ldg(&esrc[e0 + E2]) * 256u;
        oagg[3] = (uint32_t)__ldg(&esrc[e1 + E2]) * 256u;
        orev[0] = (uint32_t)__ldg(&g_soe[e0 + E2]);
        orev[1] = (uint32_t)__ldg(&g_soe[e1 + E2]);
        orev[2] = (uint32_t)__ldg(&g_soe[e0]);
        orev[3] = (uint32_t)__ldg(&g_soe[e1]);

        float acc[2][8][4];
#pragma unroll
        for (int mb = 0; mb < 2; mb++)
#pragma unroll
            for (int nb = 0; nb < 8; nb++)
#pragma unroll
                for (int c = 0; c < 4; c++) acc[mb][nb][c] = 0.f;

#pragma unroll 2
        for (int kb = 0; kb < 4; kb++) {
            const uint32_t foff = (uint32_t)kb * 64u + (uint32_t)q * 8u;
            // ef pairs for all 4 rows (also serve as partner rev data)
            float2 xf[4][2];
#pragma unroll
            for (int j = 0; j < 4; j++) {
                xf[j][0] = *(const float2*)((const char*)ef + (oef[j] + foff));
                xf[j][1] = *(const float2*)((const char*)ef + (oef[j] + foff + 32u));
            }
            // ---- phase A: W block kb (h = ef) ----
#pragma unroll
            for (int mb = 0; mb < 2; mb++) {
                uint32_t ah[4], al[4];
                cvt_split(xf[2 * mb + 0][0], ah[0], al[0]);
                cvt_split(xf[2 * mb + 1][0], ah[1], al[1]);
                cvt_split(xf[2 * mb + 0][1], ah[2], al[2]);
                cvt_split(xf[2 * mb + 1][1], ah[3], al[3]);
#pragma unroll
                for (int nb = 0; nb < 8; nb++) {
                    uint4 b = Bf[kb][nb][lane];
                    mma16816(acc[mb][nb], ah, b.x, b.y);
                    mma16816(acc[mb][nb], al, b.x, b.y);
                    mma16816(acc[mb][nb], ah, b.z, b.w);
                }
            }
            // ---- phase B: W block kb+4 (h = agg[src] - rev) ----
#pragma unroll
            for (int mb = 0; mb < 2; mb++) {
                uint32_t ah[4], al[4];
#pragma unroll
                for (int j2 = 0; j2 < 2; j2++) {
                    int j = 2 * mb + j2;
                    float2 a0 = *(const float2*)((const char*)g_agg + (oagg[j] + foff));
                    float2 a1 = *(const float2*)((const char*)g_agg + (oagg[j] + foff + 32u));
                    float2 r0, r1;
                    if (orev[j] != 0xFFFFFFFFu) {
                        r0 = *(const float2*)((const char*)g_dupsum + (orev[j] + foff));
                        r1 = *(const float2*)((const char*)g_dupsum + (orev[j] + foff + 32u));
                    } else {
                        r0 = xf[j ^ 2][0];
                        r1 = xf[j ^ 2][1];
                    }
                    cvt_split(make_float2(a0.x - r0.x, a0.y - r0.y), ah[j2], al[j2]);
                    cvt_split(make_float2(a1.x - r1.x, a1.y - r1.y), ah[2 + j2], al[2 + j2]);
                }
#pragma unroll
                for (int nb = 0; nb < 8; nb++) {
                    uint4 b = Bf[kb + 4][nb][lane];
                    mma16816(acc[mb][nb], ah, b.x, b.y);
                    mma16816(acc[mb][nb], al, b.x, b.y);
                    mma16816(acc[mb][nb], ah, b.z, b.w);
                }
            }
        }

        // ---- epilogue: bias + relu + float4 stores (N-permuted) ----
        // mb=0 -> first-half rows {e0 (c0,c1), e1 (c2,c3)}, mb=1 -> mirrors (+E2).
#pragma unroll
        for (int mb = 0; mb < 2; mb++) {
            size_t ra = (size_t)(mb == 0 ? e0 : e0 + E2) * 64;
            size_t rb = (size_t)(mb == 0 ? e1 : e1 + E2) * 64;
#pragma unroll
            for (int tt = 0; tt < 4; tt++) {
                int col = tt * 16 + 4 * q;
                float4 b4 = __ldg((const float4*)(bias + col));
                if (v0) {
                    float4 o;
                    o.x = fmaxf(acc[mb][2 * tt][0] + b4.x, 0.f);
                    o.y = fmaxf(acc[mb][2 * tt][1] + b4.y, 0.f);
                    o.z = fmaxf(acc[mb][2 * tt + 1][0] + b4.z, 0.f);
                    o.w = fmaxf(acc[mb][2 * tt + 1][1] + b4.w, 0.f);
                    *(float4*)(out + ra + col) = o;
                }
                if (v1) {
                    float4 o;
                    o.x = fmaxf(acc[mb][2 * tt][2] + b4.x, 0.f);
                    o.y = fmaxf(acc[mb][2 * tt][3] + b4.y, 0.f);
                    o.z = fmaxf(acc[mb][2 * tt + 1][2] + b4.z, 0.f);
                    o.w = fmaxf(acc[mb][2 * tt + 1][3] + b4.w, 0.f);
                    *(float4*)(out + rb + col) = o;
                }
            }
        }
    }
}

// ---------------- launch ----------------
extern "C" void kernel_launch(void* const* d_in, const int* in_sizes, int n_in,
                              void* d_out, int out_size) {
    const float* ef   = (const float*)d_in[0];
    const int*   esrc = (const int*)d_in[1];
    const int*   edst = (const int*)d_in[2];
    const float* W    = (const float*)d_in[5];
    const float* bias = (const float*)d_in[6];
    float* out = (float*)d_out;

    int E  = in_sizes[1];
    int nn = in_sizes[3];

    void *p_hkey, *p_flag, *p_agg, *p_dupid, *p_dupsum, *p_ndup;
    cudaGetSymbolAddress(&p_hkey,   g_hkey);
    cudaGetSymbolAddress(&p_flag,   g_dupflag);
    cudaGetSymbolAddress(&p_agg,    g_agg);
    cudaGetSymbolAddress(&p_dupid,  g_dupid);
    cudaGetSymbolAddress(&p_dupsum, g_dupsum);
    cudaGetSymbolAddress(&p_ndup,   g_ndup);

    cudaMemsetAsync(p_hkey,   0xFF, (size_t)TSIZE * 4);
    cudaMemsetAsync(p_flag,   0x00, (size_t)TSIZE);
    cudaMemsetAsync(p_agg,    0x00, (size_t)nn * 64 * 4);
    cudaMemsetAsync(p_dupid,  0xFF, (size_t)TSIZE * 4);
    cudaMemsetAsync(p_dupsum, 0x00, (size_t)DUPCAP * 64 * 4);
    cudaMemsetAsync(p_ndup,   0x00, 4);

    k_hash<<<(E + 255) / 256, 256>>>(esrc, edst, nn, E);
    k_aggdup<<<592, 256>>>(ef, edst, E);

    k_fused_mma<<<296, 256>>>(ef, esrc, W, bias, out, E);
}

// round 10
// speedup vs baseline: 1.1254x; 1.1254x over previous
#include <cuda_runtime.h>
#include <cuda_fp16.h>
#include <cstdint>

// ---------------- static scratch ----------------
#define TBITS 21
#define TSIZE (1u << TBITS)
#define TMASK (TSIZE - 1u)
#define EMPTYK 0xFFFFFFFFu
#define MAXE 1050624
#define MAXN 40960
#define DUPCAP 65536

__device__ unsigned int  g_hkey[TSIZE];
__device__ unsigned char g_dupflag[TSIZE];
__device__ int           g_dupid[TSIZE];
__device__ int           g_soe[MAXE];   // pass1: slot of edge; pass2: rev-offset code
__device__ __align__(16) float g_agg[MAXN * 64];
__device__ __align__(16) float g_dupsum[(size_t)DUPCAP * 64];
__device__ int           g_ndup;

// ---------------- helpers ----------------
__device__ __forceinline__ unsigned int mixh(unsigned int x) {
    x ^= x >> 16; x *= 0x7feb352du;
    x ^= x >> 15; x *= 0x846ca68bu;
    x ^= x >> 16; return x;
}

__device__ __forceinline__ void red4(float* p, float4 v) {
    asm volatile("red.global.add.v4.f32 [%0], {%1,%2,%3,%4};"
                 :: "l"(p), "f"(v.x), "f"(v.y), "f"(v.z), "f"(v.w) : "memory");
}

// fp16 split: x -> hi(f16x2) + lo(f16x2 of residual); elem .x in low half
__device__ __forceinline__ void cvt_split(float2 x, uint32_t& hi, uint32_t& lo) {
    __half2 h = __float22half2_rn(x);
    float2 hb = __half22float2(h);
    __half2 l = __floats2half2_rn(x.x - hb.x, x.y - hb.y);
    hi = *(uint32_t*)&h;
    lo = *(uint32_t*)&l;
}

__device__ __forceinline__ void mma16816(float* c, const uint32_t* a,
                                         uint32_t b0, uint32_t b1) {
    asm("mma.sync.aligned.m16n8k16.row.col.f32.f16.f16.f32 "
        "{%0,%1,%2,%3}, {%4,%5,%6,%7}, {%8,%9}, {%0,%1,%2,%3};"
        : "+f"(c[0]), "+f"(c[1]), "+f"(c[2]), "+f"(c[3])
        : "r"(a[0]), "r"(a[1]), "r"(a[2]), "r"(a[3]), "r"(b0), "r"(b1));
}

// ---------------- kernel: hash insert (thread per edge) ----------------
__global__ __launch_bounds__(256) void k_hash(const int* __restrict__ esrc,
                                              const int* __restrict__ edst,
                                              int nn, int E) {
    int i = blockIdx.x * 256 + threadIdx.x;
    if (i >= E) return;
    int s = esrc[i], d = edst[i];
    unsigned int key = (unsigned int)s * (unsigned int)nn + (unsigned int)d;
    unsigned int h = mixh(key) & TMASK;
    for (;;) {
        unsigned int prev = atomicCAS(&g_hkey[h], EMPTYK, key);
        if (prev == EMPTYK) break;
        if (prev == key) { g_dupflag[h] = 1; break; }
        h = (h + 1u) & TMASK;
    }
    g_soe[i] = (int)h;
}

// ---------------- kernel: coalesced v4 aggregation + dup claim/acc + rev encode ------
// Warp-per-32-edges. Aggregation: 16 lanes x float4 cover one 256B row; one
// LDG.128 + red.v4 warp-instruction covers TWO rows.
__global__ __launch_bounds__(256) void k_aggdup(const float* __restrict__ ef,
                                                const int* __restrict__ edst,
                                                int E) {
    const int lane = threadIdx.x & 31;
    const int wid  = threadIdx.x >> 5;
    const int nw   = gridDim.x * 8;
    const int half = lane >> 4;          // 0: row j, 1: row j+1
    const int col  = (lane & 15) * 4;    // float index within row

    for (int base = (blockIdx.x * 8 + wid) * 32; base < E; base += nw * 32) {
        int e = base + lane;
        bool v = e < E;
        int dst = v ? __ldg(&edst[e]) : 0;

        // ---- dup handling (per-thread, scattered but rare) ----
        if (v) {
            int slot = g_soe[e];
            int enc = -1;
            if (g_dupflag[slot]) {
                int d = g_dupid[slot];
                if (d < 0) {
                    int my = atomicAdd(&g_ndup, 1);
                    int old = atomicCAS(&g_dupid[slot], -1, my);
                    d = (old == -1) ? my : old;
                }
                if (d < DUPCAP) {
                    enc = d * 256;
                    const float4* row = (const float4*)(ef + (size_t)e * 64);
                    float* p = g_dupsum + (size_t)d * 64;
#pragma unroll
                    for (int c = 0; c < 16; c++) red4(p + 4 * c, row[c]);
                }
            }
            g_soe[e] = enc;
        }

        // ---- coalesced aggregation: 2 rows per warp-instruction ----
        int nvalid = min(32, E - base);
#pragma unroll 4
        for (int j = 0; j < 32; j += 2) {
            if (j >= nvalid) break;
            int r = j + half;
            int dj = __shfl_sync(0xFFFFFFFFu, dst, r);
            if (r < nvalid) {
                float4 x = *(const float4*)(ef + (size_t)(base + r) * 64 + col);
                red4(g_agg + (size_t)dj * 64 + col, x);
            }
        }
    }
}

// ---------------- fused: direct-fragment HMMA (R8, unchanged) ----------
// Per warp: M=32 edges x N=64, K=128 (h = [ef | agg[src]-rev]).
// A fragments generated directly from gmem; W fragments in SMEM.
// 3-product fp16 split: xh*wh + xl*wh + xh*wl.
__global__ __launch_bounds__(256, 2) void k_fused_mma(const float* __restrict__ ef,
                                                      const int* __restrict__ esrc,
                                                      const float* __restrict__ W,
                                                      const float* __restrict__ bias,
                                                      float* __restrict__ out, int E) {
    __shared__ uint2 Bf[2][8][8][32];   // [split][kb][nb][lane] = (b0,b1)  32KB

    const int tid  = threadIdx.x;
    const int lane = tid & 31;
    const int wid  = tid >> 5;
    const int q    = lane & 3;     // k-pair selector within fragment
    const int g    = lane >> 2;    // row-in-group

    // Build W fragments (hi & lo splits) in the exact mma B register layout.
    for (int idx = tid; idx < 4096; idx += 256) {
        int split = idx >> 11, kb = (idx >> 8) & 7, nb = (idx >> 5) & 7, L = idx & 31;
        int qq = L & 3, n = nb * 8 + (L >> 2);
        int k0 = kb * 16 + 2 * qq;
        float w00 = W[k0 * 64 + n],       w01 = W[(k0 + 1) * 64 + n];
        float w10 = W[(k0 + 8) * 64 + n], w11 = W[(k0 + 9) * 64 + n];
        uint32_t h0, l0, h1, l1;
        cvt_split(make_float2(w00, w01), h0, l0);
        cvt_split(make_float2(w10, w11), h1, l1);
        Bf[split][kb][nb][L] = (split == 0) ? make_uint2(h0, h1) : make_uint2(l0, l1);
    }
    __syncthreads();

    const int E2 = E >> 1;
    const int nwt = (E + 31) >> 5;

    for (int wt = blockIdx.x * 8 + wid; wt < nwt; wt += gridDim.x * 8) {
        const int e0 = wt * 32;

        const float2* efp[4];
        const float2* srcp[4];
        const float2* revp[4];
        bool val[4];
#pragma unroll
        for (int j = 0; j < 4; j++) {
            int e = e0 + g + 8 * j;
            val[j] = e < E;
            int ec = val[j] ? e : E - 1;
            efp[j]  = (const float2*)(ef + (size_t)ec * 64);
            srcp[j] = (const float2*)(g_agg + (size_t)__ldg(&esrc[ec]) * 64);
            int mm = (ec < E2) ? (ec + E2) : (ec - E2);
            int enc = __ldg(&g_soe[mm]);    // -1 or byte offset into g_dupsum
            revp[j] = (enc >= 0) ? (const float2*)((const char*)g_dupsum + (uint32_t)enc)
                                 : (const float2*)(ef + (size_t)mm * 64);
        }

        float acc[2][8][4];
#pragma unroll
        for (int mb = 0; mb < 2; mb++)
#pragma unroll
            for (int nb = 0; nb < 8; nb++)
#pragma unroll
                for (int c = 0; c < 4; c++) acc[mb][nb][c] = 0.f;

#pragma unroll
        for (int kb = 0; kb < 8; kb++) {
            uint32_t ah[2][4], al[2][4];
#pragma unroll
            for (int mb = 0; mb < 2; mb++) {
#pragma unroll
                for (int j2 = 0; j2 < 2; j2++) {
                    int j = mb * 2 + j2;
                    float2 x0, x1;
                    if (kb < 4) {
                        x0 = efp[j][kb * 8 + q];
                        x1 = efp[j][kb * 8 + q + 4];
                    } else {
                        int kk = kb - 4;
                        float2 a0 = srcp[j][kk * 8 + q];
                        float2 r0 = revp[j][kk * 8 + q];
                        float2 a1 = srcp[j][kk * 8 + q + 4];
                        float2 r1 = revp[j][kk * 8 + q + 4];
                        x0 = make_float2(a0.x - r0.x, a0.y - r0.y);
                        x1 = make_float2(a1.x - r1.x, a1.y - r1.y);
                    }
                    cvt_split(x0, ah[mb][0 + j2], al[mb][0 + j2]);
                    cvt_split(x1, ah[mb][2 + j2], al[mb][2 + j2]);
                }
            }
#pragma unroll
            for (int nb = 0; nb < 8; nb++) {
                uint2 bh = Bf[0][kb][nb][lane];
                uint2 bl = Bf[1][kb][nb][lane];
#pragma unroll
                for (int mb = 0; mb < 2; mb++) {
                    mma16816(acc[mb][nb], ah[mb], bh.x, bh.y);   // xh*wh
                    mma16816(acc[mb][nb], al[mb], bh.x, bh.y);   // xl*wh
                    mma16816(acc[mb][nb], ah[mb], bl.x, bl.y);   // xh*wl
                }
            }
        }

        // epilogue: bias + relu, coalesced-sector stores
#pragma unroll
        for (int mb = 0; mb < 2; mb++) {
#pragma unroll
            for (int nb = 0; nb < 8; nb++) {
                int col = nb * 8 + 2 * q;
                float2 bv = __ldg((const float2*)(bias + col));
                if (val[mb * 2]) {
                    float2 o = make_float2(fmaxf(acc[mb][nb][0] + bv.x, 0.f),
                                           fmaxf(acc[mb][nb][1] + bv.y, 0.f));
                    *(float2*)(out + (size_t)(e0 + mb * 16 + g) * 64 + col) = o;
                }
                if (val[mb * 2 + 1]) {
                    float2 o = make_float2(fmaxf(acc[mb][nb][2] + bv.x, 0.f),
                                           fmaxf(acc[mb][nb][3] + bv.y, 0.f));
                    *(float2*)(out + (size_t)(e0 + mb * 16 + g + 8) * 64 + col) = o;
                }
            }
        }
    }
}

// ---------------- launch ----------------
extern "C" void kernel_launch(void* const* d_in, const int* in_sizes, int n_in,
                              void* d_out, int out_size) {
    const float* ef   = (const float*)d_in[0];
    const int*   esrc = (const int*)d_in[1];
    const int*   edst = (const int*)d_in[2];
    const float* W    = (const float*)d_in[5];
    const float* bias = (const float*)d_in[6];
    float* out = (float*)d_out;

    int E  = in_sizes[1];
    int nn = in_sizes[3];

    void *p_hkey, *p_flag, *p_agg, *p_dupid, *p_dupsum, *p_ndup;
    cudaGetSymbolAddress(&p_hkey,   g_hkey);
    cudaGetSymbolAddress(&p_flag,   g_dupflag);
    cudaGetSymbolAddress(&p_agg,    g_agg);
    cudaGetSymbolAddress(&p_dupid,  g_dupid);
    cudaGetSymbolAddress(&p_dupsum, g_dupsum);
    cudaGetSymbolAddress(&p_ndup,   g_ndup);

    cudaMemsetAsync(p_hkey,   0xFF, (size_t)TSIZE * 4);
    cudaMemsetAsync(p_flag,   0x00, (size_t)TSIZE);
    cudaMemsetAsync(p_agg,    0x00, (size_t)nn * 64 * 4);
    cudaMemsetAsync(p_dupid,  0xFF, (size_t)TSIZE * 4);
    cudaMemsetAsync(p_dupsum, 0x00, (size_t)DUPCAP * 64 * 4);
    cudaMemsetAsync(p_ndup,   0x00, 4);

    k_hash<<<(E + 255) / 256, 256>>>(esrc, edst, nn, E);
    k_aggdup<<<592, 256>>>(ef, edst, E);

    k_fused_mma<<<296, 256>>>(ef, esrc, W, bias, out, E);
}